// round 4
// baseline (speedup 1.0000x reference)
#include <cuda_runtime.h>
#include <math_constants.h>

// Problem shape (fixed by the dataset)
#define NB 8192
#define NV 32000
#define NV4 (NV / 4)        // 8000 float4 per row
#define THREADS 256

// Graph-capturable scratch: __device__ globals, no allocation.
__device__ double g_acc;
__device__ int    g_y_is64;   // 1 if y buffer is int64, 0 if int32

// Init: zero accumulator + detect y dtype.
// Safe under both layouts: we only touch the first 8192 int32 words, which is
// exactly the int32 buffer, or the first half of an int64 buffer.
// int64 labels in [0,32000) have all odd (high) words == 0; int32 random
// labels make odd words nonzero with probability ~1.
__global__ void wce_init_kernel(const int* __restrict__ y32) {
    __shared__ int ok;
    if (threadIdx.x == 0) { g_acc = 0.0; ok = 1; }
    __syncthreads();
    for (int i = threadIdx.x; i < NB / 2; i += blockDim.x) {
        if (y32[2 * i + 1] != 0) ok = 0;   // benign race: only writes 0
    }
    __syncthreads();
    if (threadIdx.x == 0) g_y_is64 = ok;
}

__global__ __launch_bounds__(THREADS)
void wce_main_kernel(const float* __restrict__ x,
                     const void* __restrict__ y,
                     const float* __restrict__ w) {
    const int row = blockIdx.x;
    const int tid = threadIdx.x;

    const float4* __restrict__ xr = reinterpret_cast<const float4*>(x + (size_t)row * NV);
    const float4* __restrict__ wr = reinterpret_cast<const float4*>(w);

    // Online weighted logsumexp: m = running max(x), s = sum w*exp(x - m)
    float m = -CUDART_INF_F;
    float s = 0.0f;

    for (int i = tid; i < NV4; i += THREADS) {
        float4 xv = xr[i];
        float4 wv = wr[i];
        float mx = fmaxf(fmaxf(xv.x, xv.y), fmaxf(xv.z, xv.w));
        if (mx > m) {
            s *= __expf(m - mx);   // s==0 on first hit, so -inf never propagates
            m = mx;
        }
        s += wv.x * __expf(xv.x - m);
        s += wv.y * __expf(xv.y - m);
        s += wv.z * __expf(xv.z - m);
        s += wv.w * __expf(xv.w - m);
    }

    // Warp reduction of (m, s) pairs
    #pragma unroll
    for (int off = 16; off > 0; off >>= 1) {
        float m2 = __shfl_xor_sync(0xFFFFFFFFu, m, off);
        float s2 = __shfl_xor_sync(0xFFFFFFFFu, s, off);
        float M  = fmaxf(m, m2);
        s = s * __expf(m - M) + s2 * __expf(m2 - M);
        m = M;
    }

    // Cross-warp reduction via shared memory (8 warps)
    __shared__ float sm_m[8];
    __shared__ float sm_s[8];
    const int wid = tid >> 5;
    const int lid = tid & 31;
    if (lid == 0) { sm_m[wid] = m; sm_s[wid] = s; }
    __syncthreads();

    if (wid == 0) {
        m = (lid < 8) ? sm_m[lid] : -CUDART_INF_F;
        s = (lid < 8) ? sm_s[lid] : 0.0f;
        #pragma unroll
        for (int off = 4; off > 0; off >>= 1) {
            float m2 = __shfl_xor_sync(0xFFFFFFFFu, m, off);
            float s2 = __shfl_xor_sync(0xFFFFFFFFu, s, off);
            float M  = fmaxf(m, m2);
            s = s * __expf(m - M) + s2 * __expf(m2 - M);
            m = M;
        }
        if (lid == 0) {
            int yi;
            if (g_y_is64) {
                yi = (int)((const long long*)y)[row];
            } else {
                yi = ((const int*)y)[row];
            }
            // Defensive clamp: no stray value can fault the gather.
            yi = min(max(yi, 0), NV - 1);
            const float gathered = x[(size_t)row * NV + (size_t)yi];
            const float lse = m + logf(s);            // accurate log, once per row
            const float per = w[yi] * (lse - gathered);
            atomicAdd(&g_acc, (double)per);
        }
    }
}

__global__ void wce_final_kernel(float* __restrict__ out) {
    out[0] = (float)g_acc;
}

extern "C" void kernel_launch(void* const* d_in, const int* in_sizes, int n_in,
                              void* d_out, int out_size) {
    const float* x = (const float*)d_in[0];
    const void*  y = d_in[1];
    const float* w = (const float*)d_in[2];
    float*       out = (float*)d_out;

    wce_init_kernel<<<1, THREADS>>>((const int*)y);
    wce_main_kernel<<<NB, THREADS>>>(x, y, w);
    wce_final_kernel<<<1, 1>>>(out);
}